// round 13
// baseline (speedup 1.0000x reference)
#include <cuda_runtime.h>
#include <cstdint>

// GCNStack: out = relu((A @ x) @ W1 + b1) @ W2 + b2   (broadcast-W FFMA2)
// CSR build + ONE persistent fused kernel (512 thr):
//   warps 8-15: gather y = A@x per 32-node tile (8 thr/row) -> smem dbl-buf
//   warps 0-7 : lane = row. Warp owns an N-slice (32 cols GEMM1 / 8 cols GEMM2)
//     and computes all 32 rows for it. W pairs arrive as 16B smem BROADCASTS
//     (one ld.shared.v2.u64 feeds 64 MACs); A is one own-row 16B load.
//     K-packed fma.rn.f32x2 (lo=even k, hi=odd k), bias folded into acc init.

#define B_CONST 4
#define CIN     64
#define HDIM    256
#define COUT    64
#define MAXN    65536
#define MAXE    2000000
#define SCAN_CHUNK 2048
#define MAXBLK  (MAXN / SCAN_CHUNK)

typedef unsigned long long ull;

static __device__ int   g_is64;
static __device__ int   g_counts[MAXN];
static __device__ int   g_rowptr[MAXN + 1];
static __device__ int   g_cursor[MAXN];
static __device__ int   g_part[MAXBLK];
static __device__ int   g_partpre[MAXBLK];
static __device__ int   g_ecol[MAXE];
static __device__ float g_eval[MAXE];

// ================= CSR build (identical to R8) =================
__device__ __forceinline__ int idx_row(const void* A, int e, int E, int is64, int N) {
    int r = is64 ? (int)((const long long*)A)[e] : ((const int*)A)[e];
    return r < 0 ? 0 : (r >= N ? N - 1 : r);
}
__device__ __forceinline__ int idx_col(const void* A, int e, int E, int is64, int N) {
    int c = is64 ? (int)((const long long*)A)[(size_t)E + e] : ((const int*)A)[(size_t)E + e];
    return c < 0 ? 0 : (c >= N ? N - 1 : c);
}

__global__ void k_zero(const int* __restrict__ A32, int E, int n) {
    __shared__ int sbad;
    int t = threadIdx.x;
    int i = blockIdx.x * blockDim.x + t;
    if (i < n) g_counts[i] = 0;
    if (blockIdx.x == 0) {
        if (t == 0) sbad = 0;
        __syncthreads();
        int cnt = E < 128 ? E : 128;
        if (t < cnt && A32[2 * t + 1] != 0) sbad = 1;
        __syncthreads();
        if (t == 0) g_is64 = !sbad;
    }
}

__global__ void k_count(const void* __restrict__ A, int E, int N) {
    int e = blockIdx.x * blockDim.x + threadIdx.x;
    if (e < E) atomicAdd(&g_counts[idx_row(A, e, E, g_is64, N)], 1);
}

__global__ __launch_bounds__(256) void k_blocksum(int N) {
    __shared__ int wsum[8];
    int b = blockIdx.x, t = threadIdx.x;
    int base = b * SCAN_CHUNK + t * 8;
    int s = 0;
#pragma unroll
    for (int i = 0; i < 8; i++) { int id = base + i; s += (id < N) ? g_counts[id] : 0; }
#pragma unroll
    for (int o = 16; o > 0; o >>= 1) s += __shfl_down_sync(0xffffffffu, s, o);
    if ((t & 31) == 0) wsum[t >> 5] = s;
    __syncthreads();
    if (t == 0) {
        int tot = 0;
#pragma unroll
        for (int w = 0; w < 8; w++) tot += wsum[w];
        g_part[b] = tot;
    }
}

__global__ void k_scanpart(int nblocks, int E, int N) {
    int lane = threadIdx.x;
    int v = (lane < nblocks) ? g_part[lane] : 0;
    int incl = v;
#pragma unroll
    for (int o = 1; o < 32; o <<= 1) {
        int u = __shfl_up_sync(0xffffffffu, incl, o);
        if (lane >= o) incl += u;
    }
    if (lane < nblocks) g_partpre[lane] = incl - v;
    if (lane == 0) g_rowptr[N] = E;
}

__global__ __launch_bounds__(256) void k_blockscan(int N) {
    __shared__ int wsum[8];
    int b = blockIdx.x, t = threadIdx.x;
    int lane = t & 31, w = t >> 5;
    int base = b * SCAN_CHUNK + t * 8;
    int v[8];
    int s = 0;
#pragma unroll
    for (int i = 0; i < 8; i++) {
        int id = base + i;
        v[i] = (id < N) ? g_counts[id] : 0;
        s += v[i];
    }
    int incl = s;
#pragma unroll
    for (int o = 1; o < 32; o <<= 1) {
        int u = __shfl_up_sync(0xffffffffu, incl, o);
        if (lane >= o) incl += u;
    }
    if (lane == 31) wsum[w] = incl;
    __syncthreads();
    if (w == 0 && lane < 8) {
        int z = wsum[lane];
#pragma unroll
        for (int o = 1; o < 8; o <<= 1) {
            int u = __shfl_up_sync(0xffu, z, o);
            if (lane >= o) z += u;
        }
        wsum[lane] = z;
    }
    __syncthreads();
    int run = g_partpre[b] + (incl - s) + (w ? wsum[w - 1] : 0);
#pragma unroll
    for (int i = 0; i < 8; i++) {
        int id = base + i;
        if (id < N) { g_rowptr[id] = run; g_cursor[id] = run; run += v[i]; }
    }
}

__global__ void k_scatter(const void* __restrict__ A, const float* __restrict__ A_val,
                          int E, int N) {
    int e = blockIdx.x * blockDim.x + threadIdx.x;
    if (e >= E) return;
    int is64 = g_is64;
    int r = idx_row(A, e, E, is64, N);
    int p = atomicAdd(&g_cursor[r], 1);
    g_ecol[p] = idx_col(A, e, E, is64, N);
    g_eval[p] = A_val[e];
}

// ================= primitives =================
__device__ __forceinline__ ull ffma2(ull a, ull b, ull c) {
    ull d;
    asm("fma.rn.f32x2 %0, %1, %2, %3;" : "=l"(d) : "l"(a), "l"(b), "l"(c));
    return d;
}
__device__ __forceinline__ float2 upk(ull v) {
    float2 r;
    asm("mov.b64 {%0, %1}, %2;" : "=f"(r.x), "=f"(r.y) : "l"(v));
    return r;
}
__device__ __forceinline__ ull lds64(uint32_t a) {
    ull v;
    asm volatile("ld.shared.b64 %0, [%1];" : "=l"(v) : "r"(a));
    return v;
}
__device__ __forceinline__ void lds128p(ull& a, ull& b, uint32_t addr) {
    asm volatile("ld.shared.v2.u64 {%0,%1}, [%2];" : "=l"(a), "=l"(b) : "r"(addr));
}
__device__ __forceinline__ void sts128(uint32_t a, float4 v) {
    asm volatile("st.shared.v4.f32 [%0], {%1,%2,%3,%4};"
                 :: "r"(a), "f"(v.x), "f"(v.y), "f"(v.z), "f"(v.w) : "memory");
}

// ---- smem layout (bytes); strides keep 16B alignment ----
// W1T: [n=256][k=64]  f32, 256B rows       @0        (64KB)
// W2T: [n=64][k=256]  f32, 1024B rows      @65536    (64KB)
// sH : [r=32] rows of 1040B                @131072   (33280)
// sY : 2 bufs x [r=32] rows of 272B        @164352   (17408)
// B1P: 256 x (b1,0) f32 pairs              @181760   (2048)
// B2P: 64 x (b2,0)                         @183808   (512)
#define OFF_W1T 0u
#define OFF_W2T 65536u
#define OFF_H   131072u
#define OFF_Y   164352u
#define OFF_B1P 181760u
#define OFF_B2P 183808u
#define YSTR    272u
#define YBUF    8704u
#define HSTR    1040u
#define SMEM_FUSED 184320

// ================= fused gather + broadcast-W FFMA2 MLP =================
__global__ __launch_bounds__(512, 1) void k_fused(
    const float* __restrict__ x,
    const float* __restrict__ W1, const float* __restrict__ b1,
    const float* __restrict__ W2, const float* __restrict__ b2,
    float* __restrict__ out, int N)
{
    extern __shared__ float smf[];
    uint32_t sb;
    asm("{ .reg .u64 tt; cvta.to.shared.u64 tt, %1; cvt.u32.u64 %0, tt; }"
        : "=r"(sb) : "l"(smf));

    int t = threadIdx.x;
    int wd = t >> 5;
    int l = t & 31;
    bool isCompute = (wd < 8);

    int nT = (N + 31) >> 5;
    int total = nT * B_CONST;

    // -------- gather: 8 threads per row, 32B (8 ch) per thread --------
    auto gather_tile = [&](int tile, int buf) {
        int gt = t - 256;
        int r = gt >> 3, l8 = gt & 7;
        int bI = tile & 3;
        int n0 = (tile >> 2) << 5;
        int node = n0 + r;
        const float4* xb = (const float4*)x + (size_t)bI * N * 16 + 2 * l8;
        float4 a0 = make_float4(0.f, 0.f, 0.f, 0.f), a1 = a0;
        if (node < N) {
            int beg = g_rowptr[node], end = g_rowptr[node + 1];
            int i = beg;
            for (; i + 2 <= end; i += 2) {
                int   c0 = g_ecol[i],   c1 = g_ecol[i + 1];
                float v0 = g_eval[i],   v1 = g_eval[i + 1];
                const float4* p0 = xb + (size_t)c0 * 16;
                const float4* p1 = xb + (size_t)c1 * 16;
                float4 q00 = p0[0], q01 = p0[1], q10 = p1[0], q11 = p1[1];
                a0.x += v0 * q00.x; a0.y += v0 * q00.y; a0.z += v0 * q00.z; a0.w += v0 * q00.w;
                a1.x += v0 * q01.x; a1.y += v0 * q01.y; a1.z += v0 * q01.z; a1.w += v0 * q01.w;
                a0.x += v1 * q10.x; a0.y += v1 * q10.y; a0.z += v1 * q10.z; a0.w += v1 * q10.w;
                a1.x += v1 * q11.x; a1.y += v1 * q11.y; a1.z += v1 * q11.z; a1.w += v1 * q11.w;
            }
            if (i < end) {
                int c = g_ecol[i]; float v = g_eval[i];
                const float4* p = xb + (size_t)c * 16;
                float4 q0 = p[0], q1 = p[1];
                a0.x += v * q0.x; a0.y += v * q0.y; a0.z += v * q0.z; a0.w += v * q0.w;
                a1.x += v * q1.x; a1.y += v * q1.y; a1.z += v * q1.z; a1.w += v * q1.w;
            }
        }
        uint32_t yrow = sb + OFF_Y + (uint32_t)buf * YBUF + (uint32_t)r * YSTR
                      + (uint32_t)l8 * 32u;
        sts128(yrow, a0);
        sts128(yrow + 16u, a1);
    };

    // -------- prologue: transpose weights, pack biases --------
    if (isCompute) {
        for (int i = t; i < 64 * 256; i += 256) {          // W1 [k][n] -> W1T [n][k]
            int k = i >> 8, n = i & 255;
            *(float*)((char*)smf + OFF_W1T + (uint32_t)n * 256u + (uint32_t)k * 4u) = W1[i];
        }
        for (int i = t; i < 256 * 64; i += 256) {          // W2 [k][n] -> W2T [n][k]
            int k = i >> 6, n = i & 63;
            *(float*)((char*)smf + OFF_W2T + (uint32_t)n * 1024u + (uint32_t)k * 4u) = W2[i];
        }
        if (t < HDIM) {
            float2* p = (float2*)((char*)smf + OFF_B1P);
            p[t] = make_float2(b1[t], 0.f);
        }
        if (t < COUT) {
            float2* p = (float2*)((char*)smf + OFF_B2P);
            p[t] = make_float2(b2[t], 0.f);
        }
    } else {
        if ((int)blockIdx.x < total) gather_tile(blockIdx.x, 0);
    }
    __syncthreads();

    // compute constants: lane = row; warp cols = [32wd,32wd+32) / [8wd,8wd+8)
    uint32_t w1a = sb + OFF_W1T + ((uint32_t)wd * 32u) * 256u;
    uint32_t w2a = sb + OFF_W2T + ((uint32_t)wd * 8u) * 1024u;
    uint32_t hrw = sb + OFF_H + (uint32_t)l * HSTR;              // own row
    uint32_t hwr = hrw + ((uint32_t)wd * 32u) * 4u;              // write slice

    int buf = 0;
    for (int tile = blockIdx.x; tile < total; tile += gridDim.x, buf ^= 1) {
        if (isCompute) {
            int bI = tile & 3;
            int n0 = (tile >> 2) << 5;
            uint32_t ya = sb + OFF_Y + (uint32_t)buf * YBUF + (uint32_t)l * YSTR;

            // ---- GEMM1: all 32 rows x this warp's 32 cols ----
            ull acc[32];
#pragma unroll
            for (int j = 0; j < 32; j++)
                acc[j] = lds64(sb + OFF_B1P + ((uint32_t)(32 * wd + j)) * 8u);

#pragma unroll 4
            for (int k4 = 0; k4 < 16; k4++) {
                ull a01, a23;
                lds128p(a01, a23, ya + (uint32_t)k4 * 16u);       // own row, 4 k
                uint32_t wk = w1a + (uint32_t)k4 * 16u;
#pragma unroll
                for (int j = 0; j < 32; j++) {
                    ull w01, w23;
                    lds128p(w01, w23, wk + (uint32_t)j * 256u);   // broadcast
                    acc[j] = ffma2(a01, w01, acc[j]);
                    acc[j] = ffma2(a23, w23, acc[j]);
                }
            }

            // ---- epi1: fold halves + relu -> sH ----
#pragma unroll
            for (int q = 0; q < 8; q++) {
                float2 p0 = upk(acc[4 * q + 0]);
                float2 p1 = upk(acc[4 * q + 1]);
                float2 p2 = upk(acc[4 * q + 2]);
                float2 p3 = upk(acc[4 * q + 3]);
                float4 h;
                h.x = fmaxf(p0.x + p0.y, 0.f);
                h.y = fmaxf(p1.x + p1.y, 0.f);
                h.z = fmaxf(p2.x + p2.y, 0.f);
                h.w = fmaxf(p3.x + p3.y, 0.f);
                sts128(hwr + (uint32_t)q * 16u, h);
            }
            asm volatile("bar.sync 1, 256;" ::: "memory");        // compute warps

            // ---- GEMM2: all 32 rows x this warp's 8 cols ----
            ull c2[8];
#pragma unroll
            for (int j = 0; j < 8; j++)
                c2[j] = lds64(sb + OFF_B2P + ((uint32_t)(8 * wd + j)) * 8u);

#pragma unroll 8
            for (int k4 = 0; k4 < 64; k4++) {
                ull a01, a23;
                lds128p(a01, a23, hrw + (uint32_t)k4 * 16u);      // own row
                uint32_t wk = w2a + (uint32_t)k4 * 16u;
#pragma unroll
                for (int j = 0; j < 8; j++) {
                    ull w01, w23;
                    lds128p(w01, w23, wk + (uint32_t)j * 1024u);  // broadcast
                    c2[j] = ffma2(a01, w01, c2[j]);
                    c2[j] = ffma2(a23, w23, c2[j]);
                }
            }

            // ---- epi2: fold halves -> out ----
            {
                int node = n0 + l;
                if (node < N) {
                    float2 p0 = upk(c2[0]), p1 = upk(c2[1]);
                    float2 p2 = upk(c2[2]), p3 = upk(c2[3]);
                    float2 p4 = upk(c2[4]), p5 = upk(c2[5]);
                    float2 p6 = upk(c2[6]), p7 = upk(c2[7]);
                    float4 oA = make_float4(p0.x + p0.y, p1.x + p1.y,
                                            p2.x + p2.y, p3.x + p3.y);
                    float4 oB = make_float4(p4.x + p4.y, p5.x + p5.y,
                                            p6.x + p6.y, p7.x + p7.y);
                    float* op = out + ((size_t)bI * N + node) * COUT + 8 * wd;
                    ((float4*)op)[0] = oA;
                    ((float4*)op)[1] = oB;
                }
            }
        } else {
            int next = tile + gridDim.x;
            if (next < total) gather_tile(next, buf ^ 1);
        }
        __syncthreads();   // sY[buf] consumed; sY[buf^1] ready; sH safe
    }
}

// ================= launch =================
extern "C" void kernel_launch(void* const* d_in, const int* in_sizes, int n_in,
                              void* d_out, int out_size) {
    const float* x  = (const float*)d_in[0];
    const void*  A  = d_in[1];
    const float* Av = (const float*)d_in[2];
    const float* W1 = (const float*)d_in[3];
    const float* b1 = (const float*)d_in[4];
    const float* W2 = (const float*)d_in[5];
    const float* b2 = (const float*)d_in[6];
    float* out = (float*)d_out;

    int E = in_sizes[1] / 2;
    int N = in_sizes[0] / (B_CONST * CIN);
    int nb = (N + SCAN_CHUNK - 1) / SCAN_CHUNK;

    k_zero<<<(N + 255) / 256, 256>>>((const int*)A, E, N);
    k_count<<<(E + 255) / 256, 256>>>(A, E, N);
    k_blocksum<<<nb, 256>>>(N);
    k_scanpart<<<1, 32>>>(nb, E, N);
    k_blockscan<<<nb, 256>>>(N);
    k_scatter<<<(E + 255) / 256, 256>>>(A, Av, E, N);

    cudaFuncSetAttribute(k_fused, cudaFuncAttributeMaxDynamicSharedMemorySize, SMEM_FUSED);
    k_fused<<<148, 512, SMEM_FUSED>>>(x, W1, b1, W2, b2, out, N);
}